// round 6
// baseline (speedup 1.0000x reference)
#include <cuda_runtime.h>
#include <cuda_bf16.h>
#include <cstdint>

// Problem constants
constexpr int Bb = 2;
constexpr int Tt = 2048;
constexpr int Dd = 2048;
constexpr int Nh = 16;
constexpr int Hd = 128;
constexpr int Ss = 2048;
constexpr float QSCALE = 0.08838834764831845f; // 1/sqrt(128)

// Scratch (device globals — no allocation allowed)
__device__ float g_q[(size_t)Bb * Tt * Dd];
__device__ float g_k[(size_t)Bb * Tt * Dd];
__device__ float g_v[(size_t)Bb * Tt * Dd];
__device__ float g_vt[(size_t)Bb * Tt * Dd];  // V transposed per head: [bn][h][s]
__device__ float g_ctx[(size_t)Bb * Tt * Dd];
__device__ float g_m[(size_t)Bb * Nh * Tt];
__device__ float g_l[(size_t)Bb * Nh * Tt];
__device__ float g_wt[(size_t)3 * Dd * Dd];   // transposed W_{q,k,v}: [n][k]

// ===========================================================================
// Helpers
// ===========================================================================
__device__ __forceinline__ uint32_t smem_u32(const void* p) {
    return (uint32_t)__cvta_generic_to_shared(p);
}
__device__ __forceinline__ void ldsm4(uint32_t* r, uint32_t addr) {
    asm volatile("ldmatrix.sync.aligned.m8n8.x4.shared.b16 {%0,%1,%2,%3}, [%4];"
                 : "=r"(r[0]), "=r"(r[1]), "=r"(r[2]), "=r"(r[3]) : "r"(addr));
}
__device__ __forceinline__ void mma_bf16(float* c, const uint32_t* a, const uint32_t* b) {
    asm volatile(
        "mma.sync.aligned.m16n8k16.row.col.f32.bf16.bf16.f32 "
        "{%0,%1,%2,%3}, {%4,%5,%6,%7}, {%8,%9}, {%0,%1,%2,%3};"
        : "+f"(c[0]), "+f"(c[1]), "+f"(c[2]), "+f"(c[3])
        : "r"(a[0]), "r"(a[1]), "r"(a[2]), "r"(a[3]), "r"(b[0]), "r"(b[1]));
}
// Markidis bf16 split of a float pair -> packed hi (bf16x2) and lo (bf16x2)
__device__ __forceinline__ void split2(float x0, float x1, uint32_t& hi, uint32_t& lo) {
    __nv_bfloat162 h2 = __floats2bfloat162_rn(x0, x1);
    float r0 = x0 - __bfloat162float(h2.x);
    float r1 = x1 - __bfloat162float(h2.y);
    __nv_bfloat162 l2 = __floats2bfloat162_rn(r0, r1);
    hi = *reinterpret_cast<uint32_t*>(&h2);
    lo = *reinterpret_cast<uint32_t*>(&l2);
}

// smem tile geometry: 128 rows x 32 bf16 (k), row stride 40 bf16 (80B).
constexpr int STR_U32 = 20;
constexpr int STR_B   = 80;
constexpr int TILE_U32 = 128 * STR_U32;  // 2560 u32
constexpr int TILE_B   = 128 * STR_B;    // 10240 bytes

constexpr int GEMM_SMEM   = 8  * TILE_B;  // 81920: A/B hi/lo x 2 bufs
constexpr int LOGITS_SMEM = 12 * TILE_B;  // 122880: Q 4 chunks hi/lo + K hi/lo x 2 bufs
constexpr int PV_SMEM     = 8  * TILE_B;

// Common per-thread index bundle for the mma skeleton
#define MMA_IDX                                                             \
    const int tid = threadIdx.x;                                            \
    const int wid = tid >> 5;                                               \
    const int l = tid & 31;                                                 \
    const int m_off = (wid & 1) * 64;                                       \
    const int n_off = (wid >> 1) * 32;                                      \
    const int lrow = tid >> 3;                                              \
    const int kq = (tid & 7) * 4;                                           \
    const uint32_t aoff = (uint32_t)((m_off + (l & 15)) * STR_B +           \
                                     ((l >> 4) << 3) * 2);                  \
    const uint32_t boff = (uint32_t)((n_off + (l & 7) + ((l >> 4) << 3)) *  \
                                     STR_B + (((l >> 3) & 1) * 8) * 2);

// Split-store one float4 into hi/lo tile pointers (u32*)
#define SPLIT_STORE(pH, pL, v, j)                                           \
    {                                                                       \
        const int sidx = (lrow + (j) * 32) * STR_U32 + (kq >> 1);           \
        uint32_t h0, h1, l0, l1;                                            \
        split2((v).x, (v).y, h0, l0);                                       \
        split2((v).z, (v).w, h1, l1);                                       \
        *reinterpret_cast<uint2*>(&(pH)[sidx]) = make_uint2(h0, h1);        \
        *reinterpret_cast<uint2*>(&(pL)[sidx]) = make_uint2(l0, l1);        \
    }

// ldmatrix + 3-term mma over one 32-k chunk; BAH.. are smem byte addresses
#define MMA_CHUNK(acc, BAH, BAL, BBH, BBL)                                  \
    _Pragma("unroll")                                                       \
    for (int ks = 0; ks < 2; ks++) {                                        \
        uint32_t Ah[4][4], Al[4][4], Bh[2][4], Bl[2][4];                    \
        _Pragma("unroll")                                                   \
        for (int mt = 0; mt < 4; mt++) {                                    \
            ldsm4(Ah[mt], (BAH) + aoff + mt * 16 * STR_B + ks * 32);        \
            ldsm4(Al[mt], (BAL) + aoff + mt * 16 * STR_B + ks * 32);        \
        }                                                                   \
        _Pragma("unroll")                                                   \
        for (int np = 0; np < 2; np++) {                                    \
            ldsm4(Bh[np], (BBH) + boff + np * 16 * STR_B + ks * 32);        \
            ldsm4(Bl[np], (BBL) + boff + np * 16 * STR_B + ks * 32);        \
        }                                                                   \
        _Pragma("unroll")                                                   \
        for (int mt = 0; mt < 4; mt++)                                      \
            _Pragma("unroll")                                               \
            for (int nt = 0; nt < 4; nt++) {                                \
                const uint32_t* bh = &Bh[nt >> 1][(nt & 1) * 2];            \
                const uint32_t* bl = &Bl[nt >> 1][(nt & 1) * 2];            \
                mma_bf16(acc[mt][nt], Ah[mt], bh);                          \
                mma_bf16(acc[mt][nt], Ah[mt], bl);                          \
                mma_bf16(acc[mt][nt], Al[mt], bh);                          \
            }                                                               \
    }

#define ACC_ZERO(acc)                                                      \
    _Pragma("unroll")                                                      \
    for (int mt = 0; mt < 4; mt++)                                         \
        _Pragma("unroll")                                                  \
        for (int nt = 0; nt < 4; nt++)                                     \
            _Pragma("unroll")                                              \
            for (int q = 0; q < 4; q++) acc[mt][nt][q] = 0.f;

// ===========================================================================
// bf16-split-3 mma.sync GEMM (projections), ping-pong double buffered.
// ===========================================================================
__device__ __forceinline__ void mma_gemm(const float* __restrict__ A,
                                         const float* __restrict__ Bt,
                                         const float* __restrict__ bias,
                                         float* __restrict__ Out,
                                         float scale, int m0, int n0)
{
    extern __shared__ uint32_t dsm[];
    MMA_IDX
    const uint32_t base = smem_u32(dsm);
    // tiles per buffer p: [Ah, Al, Bh, Bl] at (p*4 + q)
    uint32_t* tAh[2] = {dsm + 0 * TILE_U32, dsm + 4 * TILE_U32};
    uint32_t* tAl[2] = {dsm + 1 * TILE_U32, dsm + 5 * TILE_U32};
    uint32_t* tBh[2] = {dsm + 2 * TILE_U32, dsm + 6 * TILE_U32};
    uint32_t* tBl[2] = {dsm + 3 * TILE_U32, dsm + 7 * TILE_U32};
    const uint32_t bAh[2] = {base + 0 * TILE_B, base + 4 * TILE_B};
    const uint32_t bAl[2] = {base + 1 * TILE_B, base + 5 * TILE_B};
    const uint32_t bBh[2] = {base + 2 * TILE_B, base + 6 * TILE_B};
    const uint32_t bBl[2] = {base + 3 * TILE_B, base + 7 * TILE_B};

    const float* pA = A + (size_t)(m0 + lrow) * Dd + kq;
    const float* pB = Bt + (size_t)(n0 + lrow) * Dd + kq;

    float acc[4][4][4];
    ACC_ZERO(acc)

    float4 va[4], vb[4];
#pragma unroll
    for (int j = 0; j < 4; j++) {
        va[j] = *reinterpret_cast<const float4*>(pA + (size_t)j * 32 * Dd);
        vb[j] = *reinterpret_cast<const float4*>(pB + (size_t)j * 32 * Dd);
    }
#pragma unroll
    for (int j = 0; j < 4; j++) {
        SPLIT_STORE(tAh[0], tAl[0], va[j], j)
        SPLIT_STORE(tBh[0], tBl[0], vb[j], j)
    }
    __syncthreads();

#pragma unroll 1
    for (int c = 0; c < 64; c++) {
        const int p = c & 1, pn = p ^ 1;
        if (c + 1 < 64) {
#pragma unroll
            for (int j = 0; j < 4; j++) {
                va[j] = *reinterpret_cast<const float4*>(pA + (size_t)j * 32 * Dd + (c + 1) * 32);
                vb[j] = *reinterpret_cast<const float4*>(pB + (size_t)j * 32 * Dd + (c + 1) * 32);
            }
        }
        MMA_CHUNK(acc, bAh[p], bAl[p], bBh[p], bBl[p])
        if (c + 1 < 64) {
#pragma unroll
            for (int j = 0; j < 4; j++) {
                SPLIT_STORE(tAh[pn], tAl[pn], va[j], j)
                SPLIT_STORE(tBh[pn], tBl[pn], vb[j], j)
            }
        }
        __syncthreads();
    }

    const int g = l >> 2, tg = l & 3;
#pragma unroll
    for (int mt = 0; mt < 4; mt++) {
        const int r0 = m0 + m_off + mt * 16 + g;
#pragma unroll
        for (int nt = 0; nt < 4; nt++) {
            const int col = n0 + n_off + nt * 8 + tg * 2;
            const float b0v = bias[col], b1v = bias[col + 1];
            *reinterpret_cast<float2*>(Out + (size_t)r0 * Dd + col) =
                make_float2((acc[mt][nt][0] + b0v) * scale, (acc[mt][nt][1] + b1v) * scale);
            *reinterpret_cast<float2*>(Out + (size_t)(r0 + 8) * Dd + col) =
                make_float2((acc[mt][nt][2] + b0v) * scale, (acc[mt][nt][3] + b1v) * scale);
        }
    }
}

__global__ __launch_bounds__(256)
void mma_proj_kernel(const float* __restrict__ X, const float* __restrict__ bq,
                     const float* __restrict__ bk, const float* __restrict__ bv)
{
    const int z = blockIdx.z;
    const float* Bt = g_wt + (size_t)z * Dd * Dd;
    const float* bias = (z == 0) ? bq : (z == 1) ? bk : bv;
    float* Out = (z == 0) ? g_q : (z == 1) ? g_k : g_v;
    const float scale = (z == 0) ? QSCALE : 1.0f;
    mma_gemm(X, Bt, bias, Out, scale, blockIdx.y * 128, blockIdx.x * 128);
}

__global__ __launch_bounds__(256)
void mma_oproj_kernel(const float* __restrict__ Wo, const float* __restrict__ ob,
                      float* __restrict__ out)
{
    mma_gemm(g_ctx, Wo, ob, out, 1.0f, blockIdx.y * 128, blockIdx.x * 128);
}

// ===========================================================================
// Logits: probs_raw = Q K^T + bias, online per-row (max, sumexp) stats.
// Q split ONCE into persistent smem (4 k-chunks); K streamed ping-pong.
// ===========================================================================
__global__ __launch_bounds__(256)
void mma_logits_kernel(const float* __restrict__ biasTS, float* __restrict__ probs)
{
    extern __shared__ uint32_t dsm[];
    __shared__ float red_m[128][4];
    __shared__ float red_s[128][4];

    const int bn = blockIdx.y;
    const int b = bn >> 4;
    const int n = bn & 15;
    const int t0 = blockIdx.x * 128;

    const float* __restrict__ Qp = g_q + (size_t)b * Tt * Dd + n * Hd;
    const float* __restrict__ Kp = g_k + (size_t)b * Tt * Dd + n * Hd;
    float* __restrict__ Lout = probs + (size_t)bn * Tt * Ss;

    MMA_IDX
    const uint32_t base = smem_u32(dsm);
    // layout: Q chunks kc: tiles (2kc, 2kc+1); K bufs p: tiles (8+2p, 9+2p)
    const int g = l >> 2, tg = l & 3;

    // Split Q once (4 chunks)
#pragma unroll
    for (int kc = 0; kc < 4; kc++) {
        float4 va[4];
#pragma unroll
        for (int j = 0; j < 4; j++)
            va[j] = *reinterpret_cast<const float4*>(
                Qp + (size_t)(t0 + lrow + j * 32) * Dd + kc * 32 + kq);
        uint32_t* qh = dsm + (2 * kc) * TILE_U32;
        uint32_t* ql = dsm + (2 * kc + 1) * TILE_U32;
#pragma unroll
        for (int j = 0; j < 4; j++) SPLIT_STORE(qh, ql, va[j], j)
    }

    // Preload K chunk 0 into buf 0
    {
        float4 vb[4];
#pragma unroll
        for (int j = 0; j < 4; j++)
            vb[j] = *reinterpret_cast<const float4*>(
                Kp + (size_t)(lrow + j * 32) * Dd + kq);
        uint32_t* kh = dsm + 8 * TILE_U32;
        uint32_t* kl = dsm + 9 * TILE_U32;
#pragma unroll
        for (int j = 0; j < 4; j++) SPLIT_STORE(kh, kl, vb[j], j)
    }
    __syncthreads();

    float mrun[4][2], srun[4][2];
#pragma unroll
    for (int mt = 0; mt < 4; mt++) {
        mrun[mt][0] = mrun[mt][1] = -1e30f;
        srun[mt][0] = srun[mt][1] = 0.f;
    }

#pragma unroll 1
    for (int st = 0; st < 16; st++) {
        const int s0 = st * 128;
        float acc[4][4][4];
        ACC_ZERO(acc)

#pragma unroll 1
        for (int kc = 0; kc < 4; kc++) {
            const int cc = st * 4 + kc;
            const int p = cc & 1, pn = p ^ 1;
            float4 vb[4];
            if (cc + 1 < 64) {
                const int st_n = (cc + 1) >> 2, kc_n = (cc + 1) & 3;
#pragma unroll
                for (int j = 0; j < 4; j++)
                    vb[j] = *reinterpret_cast<const float4*>(
                        Kp + (size_t)(st_n * 128 + lrow + j * 32) * Dd + kc_n * 32 + kq);
            }
            MMA_CHUNK(acc, base + (2 * kc) * TILE_B, base + (2 * kc + 1) * TILE_B,
                      base + (8 + 2 * p) * TILE_B, base + (9 + 2 * p) * TILE_B)
            if (cc + 1 < 64) {
                uint32_t* kh = dsm + (8 + 2 * pn) * TILE_U32;
                uint32_t* kl = dsm + (9 + 2 * pn) * TILE_U32;
#pragma unroll
                for (int j = 0; j < 4; j++) SPLIT_STORE(kh, kl, vb[j], j)
            }
            __syncthreads();
        }

        // Epilogue: bias add, raw-logit store, running row stats
#pragma unroll
        for (int mt = 0; mt < 4; mt++) {
            const int r1 = t0 + m_off + mt * 16 + g;
            const int r2 = r1 + 8;
            float v1[8], v2[8];
#pragma unroll
            for (int nt = 0; nt < 4; nt++) {
                const int col = s0 + n_off + nt * 8 + tg * 2;
                float2 c1 = *reinterpret_cast<const float2*>(biasTS + (size_t)r1 * Ss + col);
                float2 c2 = *reinterpret_cast<const float2*>(biasTS + (size_t)r2 * Ss + col);
                v1[nt * 2 + 0] = acc[mt][nt][0] + c1.x;
                v1[nt * 2 + 1] = acc[mt][nt][1] + c1.y;
                v2[nt * 2 + 0] = acc[mt][nt][2] + c2.x;
                v2[nt * 2 + 1] = acc[mt][nt][3] + c2.y;
                *reinterpret_cast<float2*>(Lout + (size_t)r1 * Ss + col) =
                    make_float2(v1[nt * 2], v1[nt * 2 + 1]);
                *reinterpret_cast<float2*>(Lout + (size_t)r2 * Ss + col) =
                    make_float2(v2[nt * 2], v2[nt * 2 + 1]);
            }
            float tm1 = v1[0], tm2 = v2[0];
#pragma unroll
            for (int q = 1; q < 8; q++) { tm1 = fmaxf(tm1, v1[q]); tm2 = fmaxf(tm2, v2[q]); }
            float mn1 = fmaxf(mrun[mt][0], tm1);
            float mn2 = fmaxf(mrun[mt][1], tm2);
            float a1 = 0.f, a2 = 0.f;
#pragma unroll
            for (int q = 0; q < 8; q++) {
                a1 += __expf(v1[q] - mn1);
                a2 += __expf(v2[q] - mn2);
            }
            srun[mt][0] = srun[mt][0] * __expf(mrun[mt][0] - mn1) + a1;
            srun[mt][1] = srun[mt][1] * __expf(mrun[mt][1] - mn2) + a2;
            mrun[mt][0] = mn1;
            mrun[mt][1] = mn2;
        }
    }

    // Reduce over the 4 lanes (tg) sharing each row, then across the 4 n-warps
#pragma unroll
    for (int mt = 0; mt < 4; mt++)
#pragma unroll
        for (int i = 0; i < 2; i++) {
            float m = mrun[mt][i], s = srun[mt][i];
#pragma unroll
            for (int o = 1; o <= 2; o <<= 1) {
                float mo = __shfl_xor_sync(0xffffffffu, m, o);
                float so = __shfl_xor_sync(0xffffffffu, s, o);
                float mn = fmaxf(m, mo);
                s = s * __expf(m - mn) + so * __expf(mo - mn);
                m = mn;
            }
            if (tg == 0) {
                const int rl = m_off + mt * 16 + g + i * 8;
                red_m[rl][wid >> 1] = m;
                red_s[rl][wid >> 1] = s;
            }
        }
    __syncthreads();
    if (tid < 128) {
        float m = red_m[tid][0], s = red_s[tid][0];
#pragma unroll
        for (int x = 1; x < 4; x++) {
            float mo = red_m[tid][x], so = red_s[tid][x];
            float mn = fmaxf(m, mo);
            s = s * __expf(m - mn) + so * __expf(mo - mn);
            m = mn;
        }
        g_m[(size_t)bn * Tt + t0 + tid] = m;
        g_l[(size_t)bn * Tt + t0 + tid] = s;
    }
}

// ===========================================================================
// Softmax (in-place on probs) + PV -> g_ctx.  A = P[t][s], B = Vt[h][s].
// Ping-pong double buffered.
// ===========================================================================
__global__ __launch_bounds__(256)
void mma_pv_kernel(float* __restrict__ probs)
{
    extern __shared__ uint32_t dsm[];
    __shared__ float sm_m[128];
    __shared__ float sm_inv[128];

    const int bn = blockIdx.y;
    const int b = bn >> 4;
    const int n = bn & 15;
    const int t0 = blockIdx.x * 128;

    float* __restrict__ Lp = probs + (size_t)bn * Tt * Ss;
    const float* __restrict__ Vt = g_vt + (size_t)bn * Hd * Tt;

    MMA_IDX
    const uint32_t base = smem_u32(dsm);
    uint32_t* tAh[2] = {dsm + 0 * TILE_U32, dsm + 4 * TILE_U32};
    uint32_t* tAl[2] = {dsm + 1 * TILE_U32, dsm + 5 * TILE_U32};
    uint32_t* tBh[2] = {dsm + 2 * TILE_U32, dsm + 6 * TILE_U32};
    uint32_t* tBl[2] = {dsm + 3 * TILE_U32, dsm + 7 * TILE_U32};
    const uint32_t bAh[2] = {base + 0 * TILE_B, base + 4 * TILE_B};
    const uint32_t bAl[2] = {base + 1 * TILE_B, base + 5 * TILE_B};
    const uint32_t bBh[2] = {base + 2 * TILE_B, base + 6 * TILE_B};
    const uint32_t bBl[2] = {base + 3 * TILE_B, base + 7 * TILE_B};

    if (tid < 128) {
        sm_m[tid] = g_m[(size_t)bn * Tt + t0 + tid];
        sm_inv[tid] = 1.0f / g_l[(size_t)bn * Tt + t0 + tid];
    }
    __syncthreads();

    const float mm[4] = {sm_m[lrow], sm_m[lrow + 32], sm_m[lrow + 64], sm_m[lrow + 96]};
    const float iv[4] = {sm_inv[lrow], sm_inv[lrow + 32], sm_inv[lrow + 64], sm_inv[lrow + 96]};

    float acc[4][4][4];
    ACC_ZERO(acc)

    // preload chunk 0
    float4 va[4], vb[4];
#pragma unroll
    for (int j = 0; j < 4; j++) {
        const int row = lrow + j * 32;
        float4 pv = *reinterpret_cast<const float4*>(Lp + (size_t)(t0 + row) * Ss + kq);
        pv.x = __expf(pv.x - mm[j]) * iv[j];
        pv.y = __expf(pv.y - mm[j]) * iv[j];
        pv.z = __expf(pv.z - mm[j]) * iv[j];
        pv.w = __expf(pv.w - mm[j]) * iv[j];
        *reinterpret_cast<float4*>(Lp + (size_t)(t0 + row) * Ss + kq) = pv;
        va[j] = pv;
        vb[j] = *reinterpret_cast<const float4*>(Vt + (size_t)row * Tt + kq);
    }
#pragma unroll
    for (int j = 0; j < 4; j++) {
        SPLIT_STORE(tAh[0], tAl[0], va[j], j)
        SPLIT_STORE(tBh[0], tBl[0], vb[j], j)
    }
    __syncthreads();

#pragma unroll 1
    for (int c = 0; c < 64; c++) {
        const int p = c & 1, pn = p ^ 1;
        if (c + 1 < 64) {
#pragma unroll
            for (int j = 0; j < 4; j++) {
                const int row = lrow + j * 32;
                float4 pv = *reinterpret_cast<const float4*>(
                    Lp + (size_t)(t0 + row) * Ss + (c + 1) * 32 + kq);
                pv.x = __expf(pv.x - mm[j]) * iv[j];
                pv.y = __expf(pv.y - mm[j]) * iv[j];
                pv.z = __expf(pv.z - mm[j]) * iv[j];
                pv.w = __expf(pv.w - mm[j]) * iv[j];
                *reinterpret_cast<float4*>(Lp + (size_t)(t0 + row) * Ss + (c + 1) * 32 + kq) = pv;
                va[j] = pv;
                vb[j] = *reinterpret_cast<const float4*>(
                    Vt + (size_t)row * Tt + (c + 1) * 32 + kq);
            }
        }
        MMA_CHUNK(acc, bAh[p], bAl[p], bBh[p], bBl[p])
        if (c + 1 < 64) {
#pragma unroll
            for (int j = 0; j < 4; j++) {
                SPLIT_STORE(tAh[pn], tAl[pn], va[j], j)
                SPLIT_STORE(tBh[pn], tBl[pn], vb[j], j)
            }
        }
        __syncthreads();
    }

    const int g = l >> 2, tg = l & 3;
#pragma unroll
    for (int mt = 0; mt < 4; mt++) {
        const int r0 = t0 + m_off + mt * 16 + g;
#pragma unroll
        for (int nt = 0; nt < 4; nt++) {
            const int col = n_off + nt * 8 + tg * 2;
            float* c1 = g_ctx + (size_t)(b * Tt + r0) * Dd + n * Hd + col;
            float* c2 = g_ctx + (size_t)(b * Tt + r0 + 8) * Dd + n * Hd + col;
            *reinterpret_cast<float2*>(c1) = make_float2(acc[mt][nt][0], acc[mt][nt][1]);
            *reinterpret_cast<float2*>(c2) = make_float2(acc[mt][nt][2], acc[mt][nt][3]);
        }
    }
}

// ===========================================================================
// One-time transposes
// ===========================================================================
__global__ void transpose_w_kernel(const float* __restrict__ Wq,
                                   const float* __restrict__ Wk,
                                   const float* __restrict__ Wv)
{
    __shared__ float ts[32][33];
    const int z = blockIdx.z;
    const float* W = (z == 0) ? Wq : (z == 1) ? Wk : Wv;
    float* Wt = g_wt + (size_t)z * Dd * Dd;
    const int bx = blockIdx.x * 32, by = blockIdx.y * 32;
    const int tx = threadIdx.x, ty = threadIdx.y;
#pragma unroll
    for (int r = 0; r < 32; r += 8)
        ts[ty + r][tx] = W[(size_t)(by + ty + r) * Dd + bx + tx];
    __syncthreads();
#pragma unroll
    for (int r = 0; r < 32; r += 8)
        Wt[(size_t)(bx + ty + r) * Dd + by + tx] = ts[tx][ty + r];
}

// g_vt[bn][h][s] = g_v[b][s][n*128+h]
__global__ void transpose_v_kernel()
{
    __shared__ float ts[32][33];
    const int bn = blockIdx.z;
    const int b = bn >> 4;
    const int n = bn & 15;
    const int s0 = blockIdx.x * 32, h0 = blockIdx.y * 32;
    const int tx = threadIdx.x, ty = threadIdx.y;
#pragma unroll
    for (int r = 0; r < 32; r += 8)
        ts[ty + r][tx] = g_v[(size_t)(b * Tt + s0 + ty + r) * Dd + n * Hd + h0 + tx];
    __syncthreads();
#pragma unroll
    for (int r = 0; r < 32; r += 8)
        g_vt[((size_t)bn * Hd + h0 + ty + r) * Tt + s0 + tx] = ts[tx][ty + r];
}

// ===========================================================================
extern "C" void kernel_launch(void* const* d_in, const int* in_sizes, int n_in,
                              void* d_out, int out_size)
{
    const float* query  = (const float*)d_in[0];
    const float* biasTS = (const float*)d_in[1];
    const float* wq = (const float*)d_in[2];
    const float* bq = (const float*)d_in[3];
    const float* wk = (const float*)d_in[4];
    const float* bk = (const float*)d_in[5];
    const float* wv = (const float*)d_in[6];
    const float* bv = (const float*)d_in[7];
    const float* wo = (const float*)d_in[8];
    const float* obias = (const float*)d_in[9];

    float* data_out  = (float*)d_out;
    float* probs_out = data_out + (size_t)Bb * Tt * Dd;

    static bool attr_done = false;
    if (!attr_done) {
        cudaFuncSetAttribute(mma_proj_kernel,
                             cudaFuncAttributeMaxDynamicSharedMemorySize, GEMM_SMEM);
        cudaFuncSetAttribute(mma_oproj_kernel,
                             cudaFuncAttributeMaxDynamicSharedMemorySize, GEMM_SMEM);
        cudaFuncSetAttribute(mma_logits_kernel,
                             cudaFuncAttributeMaxDynamicSharedMemorySize, LOGITS_SMEM);
        cudaFuncSetAttribute(mma_pv_kernel,
                             cudaFuncAttributeMaxDynamicSharedMemorySize, PV_SMEM);
        attr_done = true;
    }

    transpose_w_kernel<<<dim3(Dd / 32, Dd / 32, 3), dim3(32, 8)>>>(wq, wk, wv);
    mma_proj_kernel<<<dim3(Dd / 128, (Bb * Tt) / 128, 3), 256, GEMM_SMEM>>>(query, bq, bk, bv);
    transpose_v_kernel<<<dim3(Tt / 32, Hd / 32, Bb * Nh), dim3(32, 8)>>>();
    mma_logits_kernel<<<dim3(Tt / 128, Bb * Nh), 256, LOGITS_SMEM>>>(biasTS, probs_out);
    mma_pv_kernel<<<dim3(Tt / 128, Bb * Nh), 256, PV_SMEM>>>(probs_out);
    mma_oproj_kernel<<<dim3(Dd / 128, (Bb * Tt) / 128), 256, GEMM_SMEM>>>(wo, obias, data_out);
}

// round 7
// speedup vs baseline: 1.4730x; 1.4730x over previous
#include <cuda_runtime.h>
#include <cuda_bf16.h>
#include <cstdint>

// Problem constants
constexpr int Bb = 2;
constexpr int Tt = 2048;
constexpr int Dd = 2048;
constexpr int Nh = 16;
constexpr int Hd = 128;
constexpr int Ss = 2048;
constexpr float QSCALE = 0.08838834764831845f; // 1/sqrt(128)

// Scratch (device globals — no allocation allowed)
__device__ float g_q[(size_t)Bb * Tt * Dd];
__device__ float g_k[(size_t)Bb * Tt * Dd];
__device__ float g_v[(size_t)Bb * Tt * Dd];
__device__ float g_vt[(size_t)Bb * Tt * Dd];  // V transposed per head: [bn][h][s]
__device__ float g_ctx[(size_t)Bb * Tt * Dd];
__device__ float g_m[(size_t)Bb * Nh * Tt];
__device__ float g_l[(size_t)Bb * Nh * Tt];
__device__ float g_wt[(size_t)3 * Dd * Dd];   // transposed W_{q,k,v}: [n][k]

// ===========================================================================
// Helpers
// ===========================================================================
__device__ __forceinline__ uint32_t smem_u32(const void* p) {
    return (uint32_t)__cvta_generic_to_shared(p);
}
__device__ __forceinline__ void ldsm4(uint32_t* r, uint32_t addr) {
    asm volatile("ldmatrix.sync.aligned.m8n8.x4.shared.b16 {%0,%1,%2,%3}, [%4];"
                 : "=r"(r[0]), "=r"(r[1]), "=r"(r[2]), "=r"(r[3]) : "r"(addr));
}
__device__ __forceinline__ void mma_bf16(float* c, const uint32_t* a, const uint32_t* b) {
    asm volatile(
        "mma.sync.aligned.m16n8k16.row.col.f32.bf16.bf16.f32 "
        "{%0,%1,%2,%3}, {%4,%5,%6,%7}, {%8,%9}, {%0,%1,%2,%3};"
        : "+f"(c[0]), "+f"(c[1]), "+f"(c[2]), "+f"(c[3])
        : "r"(a[0]), "r"(a[1]), "r"(a[2]), "r"(a[3]), "r"(b[0]), "r"(b[1]));
}
// Markidis bf16 split of a float pair -> packed hi (bf16x2) and lo (bf16x2)
__device__ __forceinline__ void split2(float x0, float x1, uint32_t& hi, uint32_t& lo) {
    __nv_bfloat162 h2 = __floats2bfloat162_rn(x0, x1);
    float r0 = x0 - __bfloat162float(h2.x);
    float r1 = x1 - __bfloat162float(h2.y);
    __nv_bfloat162 l2 = __floats2bfloat162_rn(r0, r1);
    hi = *reinterpret_cast<uint32_t*>(&h2);
    lo = *reinterpret_cast<uint32_t*>(&l2);
}

// smem tile geometry: 128 rows x 32 bf16 (k), row stride 40 bf16 (80B).
constexpr int STR_U32 = 20;
constexpr int STR_B   = 80;
constexpr int TILE_U32 = 128 * STR_U32;  // 2560 u32
constexpr int TILE_B   = 128 * STR_B;    // 10240 bytes

constexpr int LOGITS_SMEM = 12 * TILE_B;  // 122880: Q 4 chunks hi/lo + K hi/lo x 2 bufs

// Common per-thread index bundle for the mma skeleton
#define MMA_IDX                                                             \
    const int tid = threadIdx.x;                                            \
    const int wid = tid >> 5;                                               \
    const int l = tid & 31;                                                 \
    const int m_off = (wid & 1) * 64;                                       \
    const int n_off = (wid >> 1) * 32;                                      \
    const int lrow = tid >> 3;                                              \
    const int kq = (tid & 7) * 4;                                           \
    const uint32_t aoff = (uint32_t)((m_off + (l & 15)) * STR_B +           \
                                     ((l >> 4) << 3) * 2);                  \
    const uint32_t boff = (uint32_t)((n_off + (l & 7) + ((l >> 4) << 3)) *  \
                                     STR_B + (((l >> 3) & 1) * 8) * 2);

// Split-store one float4 into hi/lo tile pointers (u32*)
#define SPLIT_STORE(pH, pL, v, j)                                           \
    {                                                                       \
        const int sidx = (lrow + (j) * 32) * STR_U32 + (kq >> 1);           \
        uint32_t h0, h1, l0, l1;                                            \
        split2((v).x, (v).y, h0, l0);                                       \
        split2((v).z, (v).w, h1, l1);                                       \
        *reinterpret_cast<uint2*>(&(pH)[sidx]) = make_uint2(h0, h1);        \
        *reinterpret_cast<uint2*>(&(pL)[sidx]) = make_uint2(l0, l1);        \
    }

// ldmatrix + 3-term mma over one 32-k chunk; BAH.. are smem byte addresses
#define MMA_CHUNK(acc, BAH, BAL, BBH, BBL)                                  \
    _Pragma("unroll")                                                       \
    for (int ks = 0; ks < 2; ks++) {                                        \
        uint32_t Ah[4][4], Al[4][4], Bh[2][4], Bl[2][4];                    \
        _Pragma("unroll")                                                   \
        for (int mt = 0; mt < 4; mt++) {                                    \
            ldsm4(Ah[mt], (BAH) + aoff + mt * 16 * STR_B + ks * 32);        \
            ldsm4(Al[mt], (BAL) + aoff + mt * 16 * STR_B + ks * 32);        \
        }                                                                   \
        _Pragma("unroll")                                                   \
        for (int np = 0; np < 2; np++) {                                    \
            ldsm4(Bh[np], (BBH) + boff + np * 16 * STR_B + ks * 32);        \
            ldsm4(Bl[np], (BBL) + boff + np * 16 * STR_B + ks * 32);        \
        }                                                                   \
        _Pragma("unroll")                                                   \
        for (int mt = 0; mt < 4; mt++)                                      \
            _Pragma("unroll")                                               \
            for (int nt = 0; nt < 4; nt++) {                                \
                const uint32_t* bh = &Bh[nt >> 1][(nt & 1) * 2];            \
                const uint32_t* bl = &Bl[nt >> 1][(nt & 1) * 2];            \
                mma_bf16(acc[mt][nt], Ah[mt], bh);                          \
                mma_bf16(acc[mt][nt], Ah[mt], bl);                          \
                mma_bf16(acc[mt][nt], Al[mt], bh);                          \
            }                                                               \
    }

#define ACC_ZERO(acc)                                                      \
    _Pragma("unroll")                                                      \
    for (int mt = 0; mt < 4; mt++)                                         \
        _Pragma("unroll")                                                  \
        for (int nt = 0; nt < 4; nt++)                                     \
            _Pragma("unroll")                                              \
            for (int q = 0; q < 4; q++) acc[mt][nt][q] = 0.f;

// ===========================================================================
// bf16-split-3 mma.sync GEMM (projections), R5 single-buffer structure.
// ===========================================================================
__device__ __forceinline__ void mma_gemm(const float* __restrict__ A,
                                         const float* __restrict__ Bt,
                                         const float* __restrict__ bias,
                                         float* __restrict__ Out,
                                         float scale, int m0, int n0)
{
    __shared__ __align__(16) uint32_t sAh[TILE_U32];
    __shared__ __align__(16) uint32_t sAl[TILE_U32];
    __shared__ __align__(16) uint32_t sBh[TILE_U32];
    __shared__ __align__(16) uint32_t sBl[TILE_U32];

    MMA_IDX
    const uint32_t SAh = smem_u32(sAh), SAl = smem_u32(sAl);
    const uint32_t SBh = smem_u32(sBh), SBl = smem_u32(sBl);

    const float* pA = A + (size_t)(m0 + lrow) * Dd + kq;
    const float* pB = Bt + (size_t)(n0 + lrow) * Dd + kq;

    float acc[4][4][4];
    ACC_ZERO(acc)

#pragma unroll 1
    for (int c = 0; c < 64; c++) {
        float4 va[4], vb[4];
#pragma unroll
        for (int j = 0; j < 4; j++) {
            va[j] = *reinterpret_cast<const float4*>(pA + (size_t)j * 32 * Dd + c * 32);
            vb[j] = *reinterpret_cast<const float4*>(pB + (size_t)j * 32 * Dd + c * 32);
        }
        __syncthreads();
#pragma unroll
        for (int j = 0; j < 4; j++) {
            SPLIT_STORE(sAh, sAl, va[j], j)
            SPLIT_STORE(sBh, sBl, vb[j], j)
        }
        __syncthreads();
        MMA_CHUNK(acc, SAh, SAl, SBh, SBl)
    }

    const int g = l >> 2, tg = l & 3;
#pragma unroll
    for (int mt = 0; mt < 4; mt++) {
        const int r0 = m0 + m_off + mt * 16 + g;
#pragma unroll
        for (int nt = 0; nt < 4; nt++) {
            const int col = n0 + n_off + nt * 8 + tg * 2;
            const float b0v = bias[col], b1v = bias[col + 1];
            *reinterpret_cast<float2*>(Out + (size_t)r0 * Dd + col) =
                make_float2((acc[mt][nt][0] + b0v) * scale, (acc[mt][nt][1] + b1v) * scale);
            *reinterpret_cast<float2*>(Out + (size_t)(r0 + 8) * Dd + col) =
                make_float2((acc[mt][nt][2] + b0v) * scale, (acc[mt][nt][3] + b1v) * scale);
        }
    }
}

__global__ __launch_bounds__(256)
void mma_proj_kernel(const float* __restrict__ X, const float* __restrict__ bq,
                     const float* __restrict__ bk, const float* __restrict__ bv)
{
    const int z = blockIdx.z;
    const float* Bt = g_wt + (size_t)z * Dd * Dd;
    const float* bias = (z == 0) ? bq : (z == 1) ? bk : bv;
    float* Out = (z == 0) ? g_q : (z == 1) ? g_k : g_v;
    const float scale = (z == 0) ? QSCALE : 1.0f;
    mma_gemm(X, Bt, bias, Out, scale, blockIdx.y * 128, blockIdx.x * 128);
}

__global__ __launch_bounds__(256)
void mma_oproj_kernel(const float* __restrict__ Wo, const float* __restrict__ ob,
                      float* __restrict__ out)
{
    mma_gemm(g_ctx, Wo, ob, out, 1.0f, blockIdx.y * 128, blockIdx.x * 128);
}

// ===========================================================================
// Logits (R6 version — measured 502us): persistent split-Q, ping-pong K.
// ===========================================================================
__global__ __launch_bounds__(256)
void mma_logits_kernel(const float* __restrict__ biasTS, float* __restrict__ probs)
{
    extern __shared__ uint32_t dsm[];
    __shared__ float red_m[128][4];
    __shared__ float red_s[128][4];

    const int bn = blockIdx.y;
    const int b = bn >> 4;
    const int n = bn & 15;
    const int t0 = blockIdx.x * 128;

    const float* __restrict__ Qp = g_q + (size_t)b * Tt * Dd + n * Hd;
    const float* __restrict__ Kp = g_k + (size_t)b * Tt * Dd + n * Hd;
    float* __restrict__ Lout = probs + (size_t)bn * Tt * Ss;

    MMA_IDX
    const uint32_t base = smem_u32(dsm);
    const int g = l >> 2, tg = l & 3;

    // Split Q once (4 chunks)
#pragma unroll
    for (int kc = 0; kc < 4; kc++) {
        float4 va[4];
#pragma unroll
        for (int j = 0; j < 4; j++)
            va[j] = *reinterpret_cast<const float4*>(
                Qp + (size_t)(t0 + lrow + j * 32) * Dd + kc * 32 + kq);
        uint32_t* qh = dsm + (2 * kc) * TILE_U32;
        uint32_t* ql = dsm + (2 * kc + 1) * TILE_U32;
#pragma unroll
        for (int j = 0; j < 4; j++) SPLIT_STORE(qh, ql, va[j], j)
    }

    // Preload K chunk 0 into buf 0
    {
        float4 vb[4];
#pragma unroll
        for (int j = 0; j < 4; j++)
            vb[j] = *reinterpret_cast<const float4*>(
                Kp + (size_t)(lrow + j * 32) * Dd + kq);
        uint32_t* kh = dsm + 8 * TILE_U32;
        uint32_t* kl = dsm + 9 * TILE_U32;
#pragma unroll
        for (int j = 0; j < 4; j++) SPLIT_STORE(kh, kl, vb[j], j)
    }
    __syncthreads();

    float mrun[4][2], srun[4][2];
#pragma unroll
    for (int mt = 0; mt < 4; mt++) {
        mrun[mt][0] = mrun[mt][1] = -1e30f;
        srun[mt][0] = srun[mt][1] = 0.f;
    }

#pragma unroll 1
    for (int st = 0; st < 16; st++) {
        const int s0 = st * 128;
        float acc[4][4][4];
        ACC_ZERO(acc)

#pragma unroll 1
        for (int kc = 0; kc < 4; kc++) {
            const int cc = st * 4 + kc;
            const int p = cc & 1, pn = p ^ 1;
            float4 vb[4];
            if (cc + 1 < 64) {
                const int st_n = (cc + 1) >> 2, kc_n = (cc + 1) & 3;
#pragma unroll
                for (int j = 0; j < 4; j++)
                    vb[j] = *reinterpret_cast<const float4*>(
                        Kp + (size_t)(st_n * 128 + lrow + j * 32) * Dd + kc_n * 32 + kq);
            }
            MMA_CHUNK(acc, base + (2 * kc) * TILE_B, base + (2 * kc + 1) * TILE_B,
                      base + (8 + 2 * p) * TILE_B, base + (9 + 2 * p) * TILE_B)
            if (cc + 1 < 64) {
                uint32_t* kh = dsm + (8 + 2 * pn) * TILE_U32;
                uint32_t* kl = dsm + (9 + 2 * pn) * TILE_U32;
#pragma unroll
                for (int j = 0; j < 4; j++) SPLIT_STORE(kh, kl, vb[j], j)
            }
            __syncthreads();
        }

        // Epilogue: bias add, raw-logit store, running row stats
#pragma unroll
        for (int mt = 0; mt < 4; mt++) {
            const int r1 = t0 + m_off + mt * 16 + g;
            const int r2 = r1 + 8;
            float v1[8], v2[8];
#pragma unroll
            for (int nt = 0; nt < 4; nt++) {
                const int col = s0 + n_off + nt * 8 + tg * 2;
                float2 c1 = *reinterpret_cast<const float2*>(biasTS + (size_t)r1 * Ss + col);
                float2 c2 = *reinterpret_cast<const float2*>(biasTS + (size_t)r2 * Ss + col);
                v1[nt * 2 + 0] = acc[mt][nt][0] + c1.x;
                v1[nt * 2 + 1] = acc[mt][nt][1] + c1.y;
                v2[nt * 2 + 0] = acc[mt][nt][2] + c2.x;
                v2[nt * 2 + 1] = acc[mt][nt][3] + c2.y;
                *reinterpret_cast<float2*>(Lout + (size_t)r1 * Ss + col) =
                    make_float2(v1[nt * 2], v1[nt * 2 + 1]);
                *reinterpret_cast<float2*>(Lout + (size_t)r2 * Ss + col) =
                    make_float2(v2[nt * 2], v2[nt * 2 + 1]);
            }
            float tm1 = v1[0], tm2 = v2[0];
#pragma unroll
            for (int q = 1; q < 8; q++) { tm1 = fmaxf(tm1, v1[q]); tm2 = fmaxf(tm2, v2[q]); }
            float mn1 = fmaxf(mrun[mt][0], tm1);
            float mn2 = fmaxf(mrun[mt][1], tm2);
            float a1 = 0.f, a2 = 0.f;
#pragma unroll
            for (int q = 0; q < 8; q++) {
                a1 += __expf(v1[q] - mn1);
                a2 += __expf(v2[q] - mn2);
            }
            srun[mt][0] = srun[mt][0] * __expf(mrun[mt][0] - mn1) + a1;
            srun[mt][1] = srun[mt][1] * __expf(mrun[mt][1] - mn2) + a2;
            mrun[mt][0] = mn1;
            mrun[mt][1] = mn2;
        }
    }

    // Reduce over the 4 lanes (tg) sharing each row, then across the 4 n-warps
#pragma unroll
    for (int mt = 0; mt < 4; mt++)
#pragma unroll
        for (int i = 0; i < 2; i++) {
            float m = mrun[mt][i], s = srun[mt][i];
#pragma unroll
            for (int o = 1; o <= 2; o <<= 1) {
                float mo = __shfl_xor_sync(0xffffffffu, m, o);
                float so = __shfl_xor_sync(0xffffffffu, s, o);
                float mn = fmaxf(m, mo);
                s = s * __expf(m - mn) + so * __expf(mo - mn);
                m = mn;
            }
            if (tg == 0) {
                const int rl = m_off + mt * 16 + g + i * 8;
                red_m[rl][wid >> 1] = m;
                red_s[rl][wid >> 1] = s;
            }
        }
    __syncthreads();
    if (tid < 128) {
        float m = red_m[tid][0], s = red_s[tid][0];
#pragma unroll
        for (int x = 1; x < 4; x++) {
            float mo = red_m[tid][x], so = red_s[tid][x];
            float mn = fmaxf(m, mo);
            s = s * __expf(m - mn) + so * __expf(mo - mn);
            m = mn;
        }
        g_m[(size_t)bn * Tt + t0 + tid] = m;
        g_l[(size_t)bn * Tt + t0 + tid] = s;
    }
}

// ===========================================================================
// Softmax (in-place on probs) + PV -> g_ctx (R5 single-buffer structure).
// ===========================================================================
__global__ __launch_bounds__(256)
void mma_pv_kernel(float* __restrict__ probs)
{
    __shared__ __align__(16) uint32_t sAh[TILE_U32];
    __shared__ __align__(16) uint32_t sAl[TILE_U32];
    __shared__ __align__(16) uint32_t sBh[TILE_U32];
    __shared__ __align__(16) uint32_t sBl[TILE_U32];
    __shared__ float sm_m[128];
    __shared__ float sm_inv[128];

    const int bn = blockIdx.y;
    const int b = bn >> 4;
    const int n = bn & 15;
    const int t0 = blockIdx.x * 128;

    float* __restrict__ Lp = probs + (size_t)bn * Tt * Ss;
    const float* __restrict__ Vt = g_vt + (size_t)bn * Hd * Tt;

    MMA_IDX
    const uint32_t SAh = smem_u32(sAh), SAl = smem_u32(sAl);
    const uint32_t SBh = smem_u32(sBh), SBl = smem_u32(sBl);

    if (tid < 128) {
        sm_m[tid] = g_m[(size_t)bn * Tt + t0 + tid];
        sm_inv[tid] = 1.0f / g_l[(size_t)bn * Tt + t0 + tid];
    }
    __syncthreads();

    const float mm[4] = {sm_m[lrow], sm_m[lrow + 32], sm_m[lrow + 64], sm_m[lrow + 96]};
    const float iv[4] = {sm_inv[lrow], sm_inv[lrow + 32], sm_inv[lrow + 64], sm_inv[lrow + 96]};

    float acc[4][4][4];
    ACC_ZERO(acc)

#pragma unroll 1
    for (int c = 0; c < 64; c++) {
        float4 va[4], vb[4];
#pragma unroll
        for (int j = 0; j < 4; j++) {
            const int row = lrow + j * 32;
            float4 pv = *reinterpret_cast<const float4*>(
                Lp + (size_t)(t0 + row) * Ss + c * 32 + kq);
            pv.x = __expf(pv.x - mm[j]) * iv[j];
            pv.y = __expf(pv.y - mm[j]) * iv[j];
            pv.z = __expf(pv.z - mm[j]) * iv[j];
            pv.w = __expf(pv.w - mm[j]) * iv[j];
            *reinterpret_cast<float4*>(Lp + (size_t)(t0 + row) * Ss + c * 32 + kq) = pv;
            va[j] = pv;
            vb[j] = *reinterpret_cast<const float4*>(
                Vt + (size_t)row * Tt + c * 32 + kq);
        }
        __syncthreads();
#pragma unroll
        for (int j = 0; j < 4; j++) {
            SPLIT_STORE(sAh, sAl, va[j], j)
            SPLIT_STORE(sBh, sBl, vb[j], j)
        }
        __syncthreads();
        MMA_CHUNK(acc, SAh, SAl, SBh, SBl)
    }

    const int g = l >> 2, tg = l & 3;
#pragma unroll
    for (int mt = 0; mt < 4; mt++) {
        const int r0 = t0 + m_off + mt * 16 + g;
#pragma unroll
        for (int nt = 0; nt < 4; nt++) {
            const int col = n_off + nt * 8 + tg * 2;
            float* c1 = g_ctx + (size_t)(b * Tt + r0) * Dd + n * Hd + col;
            float* c2 = g_ctx + (size_t)(b * Tt + r0 + 8) * Dd + n * Hd + col;
            *reinterpret_cast<float2*>(c1) = make_float2(acc[mt][nt][0], acc[mt][nt][1]);
            *reinterpret_cast<float2*>(c2) = make_float2(acc[mt][nt][2], acc[mt][nt][3]);
        }
    }
}

// ===========================================================================
// One-time transposes
// ===========================================================================
__global__ void transpose_w_kernel(const float* __restrict__ Wq,
                                   const float* __restrict__ Wk,
                                   const float* __restrict__ Wv)
{
    __shared__ float ts[32][33];
    const int z = blockIdx.z;
    const float* W = (z == 0) ? Wq : (z == 1) ? Wk : Wv;
    float* Wt = g_wt + (size_t)z * Dd * Dd;
    const int bx = blockIdx.x * 32, by = blockIdx.y * 32;
    const int tx = threadIdx.x, ty = threadIdx.y;
#pragma unroll
    for (int r = 0; r < 32; r += 8)
        ts[ty + r][tx] = W[(size_t)(by + ty + r) * Dd + bx + tx];
    __syncthreads();
#pragma unroll
    for (int r = 0; r < 32; r += 8)
        Wt[(size_t)(bx + ty + r) * Dd + by + tx] = ts[tx][ty + r];
}

// g_vt[bn][h][s] = g_v[b][s][n*128+h]
__global__ void transpose_v_kernel()
{
    __shared__ float ts[32][33];
    const int bn = blockIdx.z;
    const int b = bn >> 4;
    const int n = bn & 15;
    const int s0 = blockIdx.x * 32, h0 = blockIdx.y * 32;
    const int tx = threadIdx.x, ty = threadIdx.y;
#pragma unroll
    for (int r = 0; r < 32; r += 8)
        ts[ty + r][tx] = g_v[(size_t)(b * Tt + s0 + ty + r) * Dd + n * Hd + h0 + tx];
    __syncthreads();
#pragma unroll
    for (int r = 0; r < 32; r += 8)
        g_vt[((size_t)bn * Hd + h0 + ty + r) * Tt + s0 + tx] = ts[tx][ty + r];
}

// ===========================================================================
extern "C" void kernel_launch(void* const* d_in, const int* in_sizes, int n_in,
                              void* d_out, int out_size)
{
    const float* query  = (const float*)d_in[0];
    const float* biasTS = (const float*)d_in[1];
    const float* wq = (const float*)d_in[2];
    const float* bq = (const float*)d_in[3];
    const float* wk = (const float*)d_in[4];
    const float* bk = (const float*)d_in[5];
    const float* wv = (const float*)d_in[6];
    const float* bv = (const float*)d_in[7];
    const float* wo = (const float*)d_in[8];
    const float* obias = (const float*)d_in[9];

    float* data_out  = (float*)d_out;
    float* probs_out = data_out + (size_t)Bb * Tt * Dd;

    static bool attr_done = false;
    if (!attr_done) {
        cudaFuncSetAttribute(mma_logits_kernel,
                             cudaFuncAttributeMaxDynamicSharedMemorySize, LOGITS_SMEM);
        attr_done = true;
    }

    transpose_w_kernel<<<dim3(Dd / 32, Dd / 32, 3), dim3(32, 8)>>>(wq, wk, wv);
    mma_proj_kernel<<<dim3(Dd / 128, (Bb * Tt) / 128, 3), 256>>>(query, bq, bk, bv);
    transpose_v_kernel<<<dim3(Tt / 32, Hd / 32, Bb * Nh), dim3(32, 8)>>>();
    mma_logits_kernel<<<dim3(Tt / 128, Bb * Nh), 256, LOGITS_SMEM>>>(biasTS, probs_out);
    mma_pv_kernel<<<dim3(Tt / 128, Bb * Nh), 256>>>(probs_out);
    mma_oproj_kernel<<<dim3(Dd / 128, (Bb * Tt) / 128), 256>>>(wo, obias, data_out);
}